// round 13
// baseline (speedup 1.0000x reference)
#include <cuda_runtime.h>
#include <cuda_fp16.h>

#define NMAX   100000
#define EMAX   1600000
#define CIN_   128
#define COUT_  64
#define SCAN_C 1024
#define NBLK_MAX 128

// Scratch (device globals — no allocation allowed).
// Invariants at entry (restored each call; static zero-init on first call):
//   g_deg == 0, g_scan_cnt == 0.
__device__ __half2 g_H2[NMAX * (COUT_ / 2)];   // H raw, then Hs = H*dinv (fp16)
__device__ float   g_dinv[NMAX];
__device__ int     g_deg[NMAX];
__device__ int     g_rowoff[NMAX];             // block-local exclusive prefix
__device__ int     g_boff[NBLK_MAX];           // per-1024-chunk global offset
__device__ int     g_bsum[NBLK_MAX];
__device__ int     g_pos[EMAX];
__device__ int     g_edge[EMAX];               // src only, CSR by dst
__device__ int     g_scan_cnt;

// ---------------------------------------------------------------------------
// A) fused GEMM(raw) + degpos, role split by block:
//    blocks [0, NG)      : GEMM tile, H = X@W + b (fp16, NO dinv — no dep on scan)
//    blocks [NG, NG+ND)  : degree count + slot record, 4 edges/thread
// ---------------------------------------------------------------------------
#define FMA2(d, a, b) asm("fma.rn.f32x2 %0, %1, %2, %3;" \
                          : "=l"(d) : "l"(a), "l"(b), "l"(d))

__global__ __launch_bounds__(256) void gemmdeg_kernel(
    const float* __restrict__ X, const float* __restrict__ W,
    const float* __restrict__ bias,
    const int* __restrict__ dst,
    int n, int E, int NG)
{
    const int tid = threadIdx.x;

    if (blockIdx.x >= NG) {
        // ---- degpos role ----
        int cid  = blockIdx.x - NG;
        int base = (cid * 256 + tid) * 4;
        if (base + 3 < E) {
            int4 d = *(const int4*)(dst + base);
            int4 p;
            p.x = atomicAdd(&g_deg[d.x], 1);
            p.y = atomicAdd(&g_deg[d.y], 1);
            p.z = atomicAdd(&g_deg[d.z], 1);
            p.w = atomicAdd(&g_deg[d.w], 1);
            *(int4*)(g_pos + base) = p;
        } else {
            for (int i = base; i < E; i++)
                g_pos[i] = atomicAdd(&g_deg[dst[i]], 1);
        }
        return;
    }

    // ---- GEMM role (raw H) ----
    __shared__ float2 Xs2[16][130];
    __shared__ float  Ws[16][64];

    const int tcol = tid & 15;
    const int trow = tid >> 4;
    const int row0 = blockIdx.x * 128;

    unsigned long long acc[8][2];
    #pragma unroll
    for (int r = 0; r < 8; r++) { acc[r][0] = 0ull; acc[r][1] = 0ull; }

    for (int k0 = 0; k0 < CIN_; k0 += 16) {
        #pragma unroll
        for (int p = 0; p < 2; p++) {
            int r  = p * 64 + (tid >> 2);
            int kq = tid & 3;
            int rr = row0 + r;
            const float* xp = X + (long)(rr < n ? rr : 0) * CIN_ + k0 + kq * 4;
            float4 v = *(const float4*)xp;
            Xs2[kq * 4 + 0][r] = make_float2(v.x, v.x);
            Xs2[kq * 4 + 1][r] = make_float2(v.y, v.y);
            Xs2[kq * 4 + 2][r] = make_float2(v.z, v.z);
            Xs2[kq * 4 + 3][r] = make_float2(v.w, v.w);
        }
        {
            int k    = tid >> 4;
            int colq = tid & 15;
            float4 v = *(const float4*)(W + (long)(k0 + k) * COUT_ + colq * 4);
            *(float4*)&Ws[k][colq * 4] = v;
        }
        __syncthreads();

        #pragma unroll
        for (int kk = 0; kk < 16; kk++) {
            ulonglong2 a01 = *(const ulonglong2*)&Xs2[kk][trow * 8 + 0];
            ulonglong2 a23 = *(const ulonglong2*)&Xs2[kk][trow * 8 + 2];
            ulonglong2 a45 = *(const ulonglong2*)&Xs2[kk][trow * 8 + 4];
            ulonglong2 a67 = *(const ulonglong2*)&Xs2[kk][trow * 8 + 6];
            ulonglong2 b   = *(const ulonglong2*)&Ws[kk][tcol * 4];
            FMA2(acc[0][0], a01.x, b.x);  FMA2(acc[0][1], a01.x, b.y);
            FMA2(acc[1][0], a01.y, b.x);  FMA2(acc[1][1], a01.y, b.y);
            FMA2(acc[2][0], a23.x, b.x);  FMA2(acc[2][1], a23.x, b.y);
            FMA2(acc[3][0], a23.y, b.x);  FMA2(acc[3][1], a23.y, b.y);
            FMA2(acc[4][0], a45.x, b.x);  FMA2(acc[4][1], a45.x, b.y);
            FMA2(acc[5][0], a45.y, b.x);  FMA2(acc[5][1], a45.y, b.y);
            FMA2(acc[6][0], a67.x, b.x);  FMA2(acc[6][1], a67.x, b.y);
            FMA2(acc[7][0], a67.y, b.x);  FMA2(acc[7][1], a67.y, b.y);
        }
        __syncthreads();
    }

    float2 bb0 = *(const float2*)(bias + tcol * 4);
    float2 bb1 = *(const float2*)(bias + tcol * 4 + 2);
    #pragma unroll
    for (int r = 0; r < 8; r++) {
        int row = row0 + trow * 8 + r;
        if (row < n) {
            float2 lo = *(const float2*)&acc[r][0];
            float2 hi = *(const float2*)&acc[r][1];
            __half2 h0 = __floats2half2_rn(lo.x + bb0.x, lo.y + bb0.y);
            __half2 h1 = __floats2half2_rn(hi.x + bb1.x, hi.y + bb1.y);
            g_H2[(long)row * 32 + tcol * 2]     = h0;
            g_H2[(long)row * 32 + tcol * 2 + 1] = h1;
        }
    }
}

// ---------------------------------------------------------------------------
// B) scan: block-local exclusive prefix of deg, dinv=rsqrt(1+deg), deg:=0;
//    last-finishing block scans the <=128 block sums into g_boff.
// ---------------------------------------------------------------------------
__global__ __launch_bounds__(256) void scan_kernel(int n) {
    __shared__ int wsum[8];
    __shared__ int is_last;
    const int b    = blockIdx.x;
    const int base = b * SCAN_C + threadIdx.x * 4;
    const int lane = threadIdx.x & 31;
    const int warp = threadIdx.x >> 5;

    int v[4];
    #pragma unroll
    for (int i = 0; i < 4; i++) {
        int idx = base + i;
        v[i] = (idx < n) ? g_deg[idx] : 0;
        if (idx < n) {
            g_dinv[idx] = rsqrtf(1.0f + (float)v[i]);
            g_deg[idx]  = 0;                    // restore invariant
        }
    }
    int tsum = v[0] + v[1] + v[2] + v[3];

    int x = tsum;
    #pragma unroll
    for (int off = 1; off < 32; off <<= 1) {
        int y = __shfl_up_sync(0xFFFFFFFFu, x, off);
        if (lane >= off) x += y;
    }
    if (lane == 31) wsum[warp] = x;
    __syncthreads();
    if (threadIdx.x == 0) {
        int run = 0;
        #pragma unroll
        for (int w = 0; w < 8; w++) { int t = wsum[w]; wsum[w] = run; run += t; }
        g_bsum[b] = run;
    }
    __syncthreads();

    int run = wsum[warp] + x - tsum;
    #pragma unroll
    for (int i = 0; i < 4; i++) {
        int idx = base + i;
        if (idx < n) g_rowoff[idx] = run;
        run += v[i];
    }

    if (threadIdx.x == 0) {
        __threadfence();
        int old = atomicAdd(&g_scan_cnt, 1);
        is_last = (old == (int)gridDim.x - 1);
    }
    __syncthreads();
    if (is_last) {
        __threadfence();
        __shared__ int sp[NBLK_MAX];
        const int t = threadIdx.x;
        const int nblk = gridDim.x;
        if (t < NBLK_MAX) sp[t] = (t < nblk) ? g_bsum[t] : 0;
        __syncthreads();
        #pragma unroll
        for (int s = 1; s < NBLK_MAX; s <<= 1) {
            int vv = 0;
            if (t < NBLK_MAX && t >= s) vv = sp[t - s];
            __syncthreads();
            if (t < NBLK_MAX) sp[t] += vv;
            __syncthreads();
        }
        if (t < nblk) g_boff[t] = (t == 0) ? 0 : sp[t - 1];
        if (t == 0) g_scan_cnt = 0;             // restore invariant
    }
}

// ---------------------------------------------------------------------------
// C) fused scaleH + CSR fill, role split by block:
//    blocks [0, NS)      : Hs = H * dinv[row]  (uint4 = 4 half2 per thread)
//    blocks [NS, NS+NF)  : fill chunk, edge[off(d)+pos] = src
// ---------------------------------------------------------------------------
__global__ __launch_bounds__(256) void scalefill_kernel(
    const int* __restrict__ src, const int* __restrict__ dst,
    int n, int E, int NS)
{
    const int tid = threadIdx.x;

    if ((int)blockIdx.x < NS) {
        // ---- scale role: one uint4 (8 cols) per thread ----
        int idx = blockIdx.x * 256 + tid;           // [0, n*8)
        if (idx < n * 8) {
            uint4* p = reinterpret_cast<uint4*>(g_H2) + idx;
            uint4 v = *p;
            float di = g_dinv[idx >> 3];
            __half2* h = reinterpret_cast<__half2*>(&v);
            #pragma unroll
            for (int i = 0; i < 4; i++) {
                float2 f = __half22float2(h[i]);
                h[i] = __floats2half2_rn(f.x * di, f.y * di);
            }
            *p = v;
        }
        return;
    }

    // ---- fill role, 4 edges/thread ----
    int cid  = blockIdx.x - NS;
    int base = (cid * 256 + tid) * 4;
    if (base + 3 < E) {
        int4 s = *(const int4*)(src + base);
        int4 d = *(const int4*)(dst + base);
        int4 p = *(const int4*)(g_pos + base);
        int o0 = g_rowoff[d.x] + g_boff[d.x >> 10] + p.x;
        int o1 = g_rowoff[d.y] + g_boff[d.y >> 10] + p.y;
        int o2 = g_rowoff[d.z] + g_boff[d.z >> 10] + p.z;
        int o3 = g_rowoff[d.w] + g_boff[d.w >> 10] + p.w;
        g_edge[o0] = s.x;
        g_edge[o1] = s.y;
        g_edge[o2] = s.z;
        g_edge[o3] = s.w;
    } else {
        for (int i = base; i < E; i++) {
            int d = dst[i];
            g_edge[g_rowoff[d] + g_boff[d >> 10] + g_pos[i]] = src[i];
        }
    }
}

// ---------------------------------------------------------------------------
// D) gather: one warp per node, one half2 per lane (64 cols).
//    int4 edge-index loads (2 per 8 edges), 32-bit addressing,
//    fp16 HADD2 tree pre-reduction, fp32 accumulate.
//    out[d] = relu( dinv[d] * ( Hs[d] + sum_e Hs[src] ) )
// ---------------------------------------------------------------------------
__global__ __launch_bounds__(256) void gather_kernel(float* __restrict__ out,
                                                     int n, int E) {
    int node = (blockIdx.x * 256 + threadIdx.x) >> 5;
    if (node >= n) return;
    int lane = threadIdx.x & 31;

    float dd = g_dinv[node];
    int   r0 = g_rowoff[node] + g_boff[node >> 10];
    int   r1 = (node + 1 < n) ? (g_rowoff[node + 1] + g_boff[(node + 1) >> 10]) : E;
    int   m  = r1 - r0;

    const __half2* hb = g_H2 + lane;                 // per-lane base
    float2 acc = __half22float2(__ldg(hb + ((unsigned)node << 5)));

    const int* ep = &g_edge[r0];
    int j = 0;

    // head: align ep+j to 16B
    int head = (4 - (r0 & 3)) & 3;
    if (head > m) head = m;
    for (; j < head; j++) {
        unsigned e = (unsigned)__ldg(ep + j) << 5;
        float2 hh = __half22float2(__ldg(hb + e));
        acc.x += hh.x;  acc.y += hh.y;
    }

    const int4* ep4 = (const int4*)(ep + j);
    int nq = (m - j) >> 2;                           // int4 batches
    int q = 0;
    for (; q + 2 <= nq; q += 2) {
        int4 A = __ldg(ep4 + q);
        int4 B = __ldg(ep4 + q + 1);
        __half2 a0 = __ldg(hb + ((unsigned)A.x << 5));
        __half2 a1 = __ldg(hb + ((unsigned)A.y << 5));
        __half2 a2 = __ldg(hb + ((unsigned)A.z << 5));
        __half2 a3 = __ldg(hb + ((unsigned)A.w << 5));
        __half2 a4 = __ldg(hb + ((unsigned)B.x << 5));
        __half2 a5 = __ldg(hb + ((unsigned)B.y << 5));
        __half2 a6 = __ldg(hb + ((unsigned)B.z << 5));
        __half2 a7 = __ldg(hb + ((unsigned)B.w << 5));
        __half2 s01 = __hadd2(a0, a1), s23 = __hadd2(a2, a3);
        __half2 s45 = __hadd2(a4, a5), s67 = __hadd2(a6, a7);
        __half2 s03 = __hadd2(s01, s23), s47 = __hadd2(s45, s67);
        float2 f0 = __half22float2(s03);
        float2 f1 = __half22float2(s47);
        acc.x += f0.x + f1.x;
        acc.y += f0.y + f1.y;
    }
    if (q < nq) {
        int4 A = __ldg(ep4 + q);
        __half2 a0 = __ldg(hb + ((unsigned)A.x << 5));
        __half2 a1 = __ldg(hb + ((unsigned)A.y << 5));
        __half2 a2 = __ldg(hb + ((unsigned)A.z << 5));
        __half2 a3 = __ldg(hb + ((unsigned)A.w << 5));
        __half2 s01 = __hadd2(a0, a1), s23 = __hadd2(a2, a3);
        float2 f0 = __half22float2(s01);
        float2 f1 = __half22float2(s23);
        acc.x += f0.x + f1.x;
        acc.y += f0.y + f1.y;
        q++;
    }
    j += nq << 2;
    for (; j < m; j++) {
        unsigned e = (unsigned)__ldg(ep + j) << 5;
        float2 hh = __half22float2(__ldg(hb + e));
        acc.x += hh.x;  acc.y += hh.y;
    }

    float2 o = make_float2(fmaxf(acc.x * dd, 0.0f), fmaxf(acc.y * dd, 0.0f));
    *(float2*)&out[(long)node * COUT_ + lane * 2] = o;
}

// ---------------------------------------------------------------------------
extern "C" void kernel_launch(void* const* d_in, const int* in_sizes, int n_in,
                              void* d_out, int out_size)
{
    const float* X    = (const float*)d_in[0];   // (N, 128)
    const float* W    = (const float*)d_in[1];   // (128, 64)
    const float* bias = (const float*)d_in[2];   // (64,)
    const int*   src  = (const int*)d_in[3];     // (E,)
    const int*   dst  = (const int*)d_in[4];     // (E,)
    float*       out  = (float*)d_out;           // (N, 64)

    const int n = in_sizes[0] / CIN_;
    const int E = in_sizes[3];
    const int nblk = (n + SCAN_C - 1) / SCAN_C;

    const int NG = (n + 127) / 128;          // gemm tiles
    const int ND = (E + 1023) / 1024;        // degpos chunks
    const int NS = (n * 8 + 255) / 256;      // scaleH blocks
    const int NF = (E + 1023) / 1024;        // fill chunks

    // A) GEMM(raw) ∥ degpos   (independent: GEMM needs no graph data)
    gemmdeg_kernel<<<NG + ND, 256>>>(X, W, bias, dst, n, E, NG);
    // B) scan -> dinv, rowoff, boff
    scan_kernel<<<nblk, 256>>>(n);
    // C) scaleH (H *= dinv) ∥ fill
    scalefill_kernel<<<NS + NF, 256>>>(src, dst, n, E, NS);
    // D) gather + ReLU
    gather_kernel<<<(int)(((long)n * 32 + 255) / 256), 256>>>(out, n, E);
}

// round 16
// speedup vs baseline: 1.1147x; 1.1147x over previous
#include <cuda_runtime.h>
#include <cuda_fp16.h>

#define NMAX   100000
#define EMAX   1600000
#define EPAD   2000000          // padded CSR capacity (E + 3N max)
#define CIN_   128
#define COUT_  64
#define SCAN_C 1024
#define NBLK_MAX 128
#define DUMMY_OFF (NMAX << 7)   // byte offset of the permanently-zero H row

// Scratch (device globals — no allocation allowed). 16B alignment is REQUIRED
// on every array accessed through a vector type (int4/uint4 casts).
// Invariants at entry (restored each call; static zero-init on first call):
//   g_deg == 0, g_scan_cnt == 0, g_sync1 == 0, g_H2 row NMAX stays zero.
__device__ __align__(16) __half2 g_H2[(NMAX + 1) * (COUT_ / 2)]; // Hs fp16; row NMAX = zeros
__device__ float   g_dinv[NMAX];
__device__ int     g_deg[NMAX];
__device__ int     g_rowoff[NMAX];             // block-local PADDED exclusive prefix
__device__ int     g_boff[NBLK_MAX];           // per-1024-chunk global offset
__device__ int     g_bsum[NBLK_MAX];
__device__ __align__(16) int g_pos[EMAX];
__device__ __align__(16) int g_edge[EPAD];     // PRE-SHIFTED byte offsets (src<<7), CSR by dst
__device__ int     g_scan_cnt;
__device__ int     g_sync1;                    // scan-complete flag
__device__ int     g_total_pad;                // total padded edge count

// ---------------------------------------------------------------------------
// acquire-spin on g_sync1 (producer uses st.release)
// ---------------------------------------------------------------------------
__device__ __forceinline__ void wait_sync1() {
    if (threadIdx.x == 0) {
        int f;
        do {
            asm volatile("ld.acquire.gpu.global.b32 %0, [%1];"
                         : "=r"(f) : "l"(&g_sync1) : "memory");
            if (!f) __nanosleep(128);
        } while (!f);
    }
    __syncthreads();
}

// ---------------------------------------------------------------------------
// 1) degree count + slot record, 4 edges/thread  (own launch — no deps)
// ---------------------------------------------------------------------------
__global__ __launch_bounds__(256) void degpos_kernel(const int* __restrict__ dst, int E) {
    int base = (blockIdx.x * 256 + threadIdx.x) * 4;
    if (base + 3 < E) {
        int4 d = *(const int4*)(dst + base);
        int4 p;
        p.x = atomicAdd(&g_deg[d.x], 1);
        p.y = atomicAdd(&g_deg[d.y], 1);
        p.z = atomicAdd(&g_deg[d.z], 1);
        p.w = atomicAdd(&g_deg[d.w], 1);
        *(int4*)(g_pos + base) = p;
    } else {
        for (int i = base; i < E; i++)
            g_pos[i] = atomicAdd(&g_deg[dst[i]], 1);
    }
}

// ---------------------------------------------------------------------------
// 2) fused launch, roles by block range:
//    [0, NSCAN)              scan: padded prefix + dinv + boff, then RELEASE g_sync1
//    [NSCAN, +NG)            gemm: Hs=(X@W+b)*dinv (spins on g_sync1 only at epilogue)
//    [.., +NF)               fill: edge[off(d)+pos] = src<<7 (spins first)
//    [.., +NP)               pad : dummy slots + deg reset (spins first)
//    Spinners only wait on strictly lower-indexed blocks -> deadlock-free.
//    NOTE: shared arrays carry __align__(16) — scan's shared vars share the
//    same shared-memory block and would otherwise shift Xs2/Ws off 16B,
//    faulting the 128-bit LDS reads (root cause of R14/R15 crashes).
// ---------------------------------------------------------------------------
#define FMA2(d, a, b) asm("fma.rn.f32x2 %0, %1, %2, %3;" \
                          : "=l"(d) : "l"(a), "l"(b), "l"(d))

__global__ __launch_bounds__(256) void fused_kernel(
    const float* __restrict__ X, const float* __restrict__ W,
    const float* __restrict__ bias,
    const int* __restrict__ src, const int* __restrict__ dst,
    int n, int E, int NSCAN, int NG, int NF)
{
    const int tid = threadIdx.x;
    const int bid = blockIdx.x;

    // ===================== scan role =====================
    if (bid < NSCAN) {
        __shared__ __align__(16) int wsum[8];
        __shared__ int is_last;
        const int b    = bid;
        const int base = b * SCAN_C + tid * 4;
        const int lane = tid & 31;
        const int warp = tid >> 5;

        int vp[4];
        #pragma unroll
        for (int i = 0; i < 4; i++) {
            int idx = base + i;
            int tv = (idx < n) ? g_deg[idx] : 0;
            if (idx < n) g_dinv[idx] = rsqrtf(1.0f + (float)tv);
            vp[i] = (tv + 3) & ~3;               // padded degree
        }
        int tsum = vp[0] + vp[1] + vp[2] + vp[3];

        int x = tsum;
        #pragma unroll
        for (int off = 1; off < 32; off <<= 1) {
            int y = __shfl_up_sync(0xFFFFFFFFu, x, off);
            if (lane >= off) x += y;
        }
        if (lane == 31) wsum[warp] = x;
        __syncthreads();
        if (tid == 0) {
            int run = 0;
            #pragma unroll
            for (int w = 0; w < 8; w++) { int t = wsum[w]; wsum[w] = run; run += t; }
            g_bsum[b] = run;
        }
        __syncthreads();

        int run = wsum[warp] + x - tsum;
        #pragma unroll
        for (int i = 0; i < 4; i++) {
            int idx = base + i;
            if (idx < n) g_rowoff[idx] = run;
            run += vp[i];
        }

        __syncthreads();
        if (tid == 0) {
            __threadfence();
            int old = atomicAdd(&g_scan_cnt, 1);
            is_last = (old == NSCAN - 1);
        }
        __syncthreads();
        if (is_last) {
            __threadfence();
            __shared__ __align__(16) int sp[NBLK_MAX];
            if (tid < NBLK_MAX) sp[tid] = (tid < NSCAN) ? g_bsum[tid] : 0;
            __syncthreads();
            #pragma unroll
            for (int s = 1; s < NBLK_MAX; s <<= 1) {
                int vv = 0;
                if (tid < NBLK_MAX && tid >= s) vv = sp[tid - s];
                __syncthreads();
                if (tid < NBLK_MAX) sp[tid] += vv;
                __syncthreads();
            }
            if (tid < NSCAN) g_boff[tid] = (tid == 0) ? 0 : sp[tid - 1];
            if (tid == 0) {
                g_total_pad = sp[NSCAN - 1];
                g_scan_cnt  = 0;                 // restore invariant
            }
            __syncthreads();
            if (tid == 0) {
                __threadfence();
                asm volatile("st.release.gpu.global.b32 [%0], %1;"
                             :: "l"(&g_sync1), "r"(1) : "memory");
            }
        }
        return;
    }

    // ===================== gemm role =====================
    if (bid < NSCAN + NG) {
        __shared__ __align__(16) float2 Xs2[16][130];
        __shared__ __align__(16) float  Ws[16][64];

        const int tcol = tid & 15;
        const int trow = tid >> 4;
        const int row0 = (bid - NSCAN) * 128;

        unsigned long long acc[8][2];
        #pragma unroll
        for (int r = 0; r < 8; r++) { acc[r][0] = 0ull; acc[r][1] = 0ull; }

        for (int k0 = 0; k0 < CIN_; k0 += 16) {
            #pragma unroll
            for (int p = 0; p < 2; p++) {
                int r  = p * 64 + (tid >> 2);
                int kq = tid & 3;
                int rr = row0 + r;
                const float* xp = X + (long)(rr < n ? rr : 0) * CIN_ + k0 + kq * 4;
                float4 v = *(const float4*)xp;
                Xs2[kq * 4 + 0][r] = make_float2(v.x, v.x);
                Xs2[kq * 4 + 1][r] = make_float2(v.y, v.y);
                Xs2[kq * 4 + 2][r] = make_float2(v.z, v.z);
                Xs2[kq * 4 + 3][r] = make_float2(v.w, v.w);
            }
            {
                int k    = tid >> 4;
                int colq = tid & 15;
                float4 v = *(const float4*)(W + (long)(k0 + k) * COUT_ + colq * 4);
                *(float4*)&Ws[k][colq * 4] = v;
            }
            __syncthreads();

            #pragma unroll
            for (int kk = 0; kk < 16; kk++) {
                ulonglong2 a01 = *(const ulonglong2*)&Xs2[kk][trow * 8 + 0];
                ulonglong2 a23 = *(const ulonglong2*)&Xs2[kk][trow * 8 + 2];
                ulonglong2 a45 = *(const ulonglong2*)&Xs2[kk][trow * 8 + 4];
                ulonglong2 a67 = *(const ulonglong2*)&Xs2[kk][trow * 8 + 6];
                ulonglong2 b   = *(const ulonglong2*)&Ws[kk][tcol * 4];
                FMA2(acc[0][0], a01.x, b.x);  FMA2(acc[0][1], a01.x, b.y);
                FMA2(acc[1][0], a01.y, b.x);  FMA2(acc[1][1], a01.y, b.y);
                FMA2(acc[2][0], a23.x, b.x);  FMA2(acc[2][1], a23.x, b.y);
                FMA2(acc[3][0], a23.y, b.x);  FMA2(acc[3][1], a23.y, b.y);
                FMA2(acc[4][0], a45.x, b.x);  FMA2(acc[4][1], a45.x, b.y);
                FMA2(acc[5][0], a45.y, b.x);  FMA2(acc[5][1], a45.y, b.y);
                FMA2(acc[6][0], a67.x, b.x);  FMA2(acc[6][1], a67.x, b.y);
                FMA2(acc[7][0], a67.y, b.x);  FMA2(acc[7][1], a67.y, b.y);
            }
            __syncthreads();
        }

        wait_sync1();                            // dinv ready (scan finished long ago)

        float2 bb0 = *(const float2*)(bias + tcol * 4);
        float2 bb1 = *(const float2*)(bias + tcol * 4 + 2);
        #pragma unroll
        for (int r = 0; r < 8; r++) {
            int row = row0 + trow * 8 + r;
            if (row < n) {
                float di = g_dinv[row];
                float2 lo = *(const float2*)&acc[r][0];
                float2 hi = *(const float2*)&acc[r][1];
                __half2 h0 = __floats2half2_rn((lo.x + bb0.x) * di, (lo.y + bb0.y) * di);
                __half2 h1 = __floats2half2_rn((hi.x + bb1.x) * di, (hi.y + bb1.y) * di);
                g_H2[(long)row * 32 + tcol * 2]     = h0;
                g_H2[(long)row * 32 + tcol * 2 + 1] = h1;
            }
        }
        return;
    }

    // ===================== fill role =====================
    if (bid < NSCAN + NG + NF) {
        wait_sync1();
        int cid  = bid - NSCAN - NG;
        int base = (cid * 256 + tid) * 4;
        if (base + 3 < E) {
            int4 s = *(const int4*)(src + base);
            int4 d = *(const int4*)(dst + base);
            int4 p = *(const int4*)(g_pos + base);
            int o0 = g_rowoff[d.x] + g_boff[d.x >> 10] + p.x;
            int o1 = g_rowoff[d.y] + g_boff[d.y >> 10] + p.y;
            int o2 = g_rowoff[d.z] + g_boff[d.z >> 10] + p.z;
            int o3 = g_rowoff[d.w] + g_boff[d.w >> 10] + p.w;
            g_edge[o0] = s.x << 7;               // pre-shifted byte offsets
            g_edge[o1] = s.y << 7;
            g_edge[o2] = s.z << 7;
            g_edge[o3] = s.w << 7;
        } else {
            for (int i = base; i < E; i++) {
                int d = dst[i];
                g_edge[g_rowoff[d] + g_boff[d >> 10] + g_pos[i]] = src[i] << 7;
            }
        }
        return;
    }

    // ===================== pad role =====================
    {
        wait_sync1();
        int cid = bid - NSCAN - NG - NF;
        int i = cid * 256 + tid;
        if (i < n) {
            int d0 = g_deg[i];
            int r  = g_rowoff[i] + g_boff[i >> 10];
            int e1 = r + ((d0 + 3) & ~3);
            for (int k = r + d0; k < e1; k++) g_edge[k] = DUMMY_OFF;
            g_deg[i] = 0;                        // restore invariant
        }
    }
}

// ---------------------------------------------------------------------------
// 3) gather: one warp per node, one half2 per lane (64 cols).
//    Padded CSR: count multiple of 4, 16B-aligned -> pure int4 index batches,
//    pre-shifted byte offsets, tree-of-8 HADD2, single widen per 8 edges.
//    out[d] = relu( dinv[d] * ( Hs[d] + sum_e Hs[src] ) )
// ---------------------------------------------------------------------------
__global__ __launch_bounds__(256) void gather_kernel(float* __restrict__ out, int n) {
    if (blockIdx.x == 0 && threadIdx.x == 0) g_sync1 = 0;   // restore invariant
    int node = (blockIdx.x * 256 + threadIdx.x) >> 5;
    if (node >= n) return;
    int lane = threadIdx.x & 31;

    float dd = g_dinv[node];
    int   r0 = g_rowoff[node] + g_boff[node >> 10];
    int   r1 = (node + 1 < n) ? (g_rowoff[node + 1] + g_boff[(node + 1) >> 10])
                              : g_total_pad;
    int   m4 = (r1 - r0) >> 2;                   // int4 batches (exact)

    const char* hbB = (const char*)g_H2 + lane * 4;
    float2 acc = __half22float2(*(const __half2*)(hbB + ((long)node << 7)));

    const int4* ep4 = (const int4*)(g_edge + r0);
    int q = 0;
    for (; q + 2 <= m4; q += 2) {
        int4 A = __ldg(ep4 + q);
        int4 B = __ldg(ep4 + q + 1);
        __half2 a0 = __ldg((const __half2*)(hbB + A.x));
        __half2 a1 = __ldg((const __half2*)(hbB + A.y));
        __half2 a2 = __ldg((const __half2*)(hbB + A.z));
        __half2 a3 = __ldg((const __half2*)(hbB + A.w));
        __half2 a4 = __ldg((const __half2*)(hbB + B.x));
        __half2 a5 = __ldg((const __half2*)(hbB + B.y));
        __half2 a6 = __ldg((const __half2*)(hbB + B.z));
        __half2 a7 = __ldg((const __half2*)(hbB + B.w));
        __half2 s01 = __hadd2(a0, a1), s23 = __hadd2(a2, a3);
        __half2 s45 = __hadd2(a4, a5), s67 = __hadd2(a6, a7);
        __half2 s03 = __hadd2(s01, s23), s47 = __hadd2(s45, s67);
        __half2 s   = __hadd2(s03, s47);
        float2 f = __half22float2(s);
        acc.x += f.x;  acc.y += f.y;
    }
    if (q < m4) {
        int4 A = __ldg(ep4 + q);
        __half2 a0 = __ldg((const __half2*)(hbB + A.x));
        __half2 a1 = __ldg((const __half2*)(hbB + A.y));
        __half2 a2 = __ldg((const __half2*)(hbB + A.z));
        __half2 a3 = __ldg((const __half2*)(hbB + A.w));
        __half2 s01 = __hadd2(a0, a1), s23 = __hadd2(a2, a3);
        __half2 s   = __hadd2(s01, s23);
        float2 f = __half22float2(s);
        acc.x += f.x;  acc.y += f.y;
    }

    float2 o = make_float2(fmaxf(acc.x * dd, 0.0f), fmaxf(acc.y * dd, 0.0f));
    *(float2*)&out[(long)node * COUT_ + lane * 2] = o;
}

// ---------------------------------------------------------------------------
extern "C" void kernel_launch(void* const* d_in, const int* in_sizes, int n_in,
                              void* d_out, int out_size)
{
    const float* X    = (const float*)d_in[0];   // (N, 128)
    const float* W    = (const float*)d_in[1];   // (128, 64)
    const float* bias = (const float*)d_in[2];   // (64,)
    const int*   src  = (const int*)d_in[3];     // (E,)
    const int*   dst  = (const int*)d_in[4];     // (E,)
    float*       out  = (float*)d_out;           // (N, 64)

    const int n = in_sizes[0] / CIN_;
    const int E = in_sizes[3];

    const int NSCAN = (n + SCAN_C - 1) / SCAN_C;   // 98
    const int NG    = (n + 127) / 128;             // 782
    const int NF    = (E + 1023) / 1024;           // 1563
    const int NP    = (n + 255) / 256;             // 391

    degpos_kernel<<<(E + 1023) / 1024, 256>>>(dst, E);
    fused_kernel<<<NSCAN + NG + NF + NP, 256>>>(X, W, bias, src, dst,
                                                n, E, NSCAN, NG, NF);
    gather_kernel<<<(int)(((long)n * 32 + 255) / 256), 256>>>(out, n);
}